// round 9
// baseline (speedup 1.0000x reference)
#include <cuda_runtime.h>

// ---------------------------------------------------------------------------
// Static device scratch (no allocations allowed).
// N = 100000 nodes, E = 1600000 edges, D = 128.
// Padded buckets: capacity 128/node (Poisson mean 16, max over 100K ~45).
// g_cur is zero at module load; gather_kernel resets it after reading, so
// every invocation (incl. graph replays) sees cur == 0 at fill entry.
// (Pattern correctness verified in R6/R7 runs.)
// ---------------------------------------------------------------------------
#define MAX_NODES 100000
#define BUCKET_CAP 128

__device__ __align__(16) int g_cur[MAX_NODES];                   // degree/cursor
__device__ __align__(16) int g_srcs[(size_t)MAX_NODES * BUCKET_CAP];

// ---------------------------------------------------------------------------
// 1. fill: drop src ids into per-dst padded buckets. 4 edges/thread via int4
//    loads -> 4 independent ATOMGs in flight. (R5-proven body)
// ---------------------------------------------------------------------------
__global__ void fill_kernel(const int4* __restrict__ src4,
                            const int4* __restrict__ dst4,
                            int* __restrict__ cur,
                            int* __restrict__ srcs, int ne4, int n_edges) {
    int i = blockIdx.x * blockDim.x + threadIdx.x;
    if (i < ne4) {
        int4 d = __ldg(dst4 + i);
        int4 s = __ldg(src4 + i);
        int p0 = atomicAdd(cur + d.x, 1);
        int p1 = atomicAdd(cur + d.y, 1);
        int p2 = atomicAdd(cur + d.z, 1);
        int p3 = atomicAdd(cur + d.w, 1);
        if (p0 < BUCKET_CAP) srcs[(size_t)d.x * BUCKET_CAP + p0] = s.x;
        if (p1 < BUCKET_CAP) srcs[(size_t)d.y * BUCKET_CAP + p1] = s.y;
        if (p2 < BUCKET_CAP) srcs[(size_t)d.z * BUCKET_CAP + p2] = s.z;
        if (p3 < BUCKET_CAP) srcs[(size_t)d.w * BUCKET_CAP + p3] = s.w;
    }
    if (i == 0) {  // tail (n_edges % 4)
        const int* src = (const int*)src4;
        const int* dst = (const int*)dst4;
        for (int e = ne4 * 4; e < n_edges; e++) {
            int d = dst[e];
            int p = atomicAdd(cur + d, 1);
            if (p < BUCKET_CAP) srcs[(size_t)d * BUCKET_CAP + p] = src[e];
        }
    }
}

// ---------------------------------------------------------------------------
// 2. gather + finalize: one warp per node, DIRECT fp32 float4 gather from the
//    input features (no fp16 table: the gather is latency-bound, so the 2x
//    byte saving never repaid the 12.7us/launch convert kernel). R5-proven
//    loop shape: unroll 4, A/B fp32 accumulators, __ldg loads.
//    Resets cur[node]=0 after reading (state for next invocation).
//    out = 0.5*x + 0.5*sum/max(deg,1), exact fp32 -> rel_err ~3e-8.
// ---------------------------------------------------------------------------
__global__ void gather_kernel(const float4* __restrict__ feats4,
                              int* __restrict__ cur,
                              const int* __restrict__ srcs,
                              float4* __restrict__ out4, int n_nodes) {
    int tid = blockIdx.x * blockDim.x + threadIdx.x;
    int node = tid >> 5;
    int lane = tid & 31;
    if (node >= n_nodes) return;

    int deg_raw = cur[node];           // broadcast load
    if (lane == 0) cur[node] = 0;      // reset for next invocation
    int deg = min(deg_raw, BUCKET_CAP);
    const int* bucket = srcs + (size_t)node * BUCKET_CAP;

    float4 accA = make_float4(0.f, 0.f, 0.f, 0.f);
    float4 accB = make_float4(0.f, 0.f, 0.f, 0.f);

    for (int base = 0; base < deg; base += 32) {
        int nchunk = min(32, deg - base);
        int idx = (lane < nchunk) ? __ldg(bucket + base + lane) : 0;
        int j = 0;
        for (; j + 4 <= nchunk; j += 4) {
            int s0 = __shfl_sync(0xffffffffu, idx, j);
            int s1 = __shfl_sync(0xffffffffu, idx, j + 1);
            int s2 = __shfl_sync(0xffffffffu, idx, j + 2);
            int s3 = __shfl_sync(0xffffffffu, idx, j + 3);
            float4 v0 = __ldg(feats4 + (size_t)s0 * 32 + lane);
            float4 v1 = __ldg(feats4 + (size_t)s1 * 32 + lane);
            float4 v2 = __ldg(feats4 + (size_t)s2 * 32 + lane);
            float4 v3 = __ldg(feats4 + (size_t)s3 * 32 + lane);
            accA.x += v0.x; accA.y += v0.y; accA.z += v0.z; accA.w += v0.w;
            accB.x += v1.x; accB.y += v1.y; accB.z += v1.z; accB.w += v1.w;
            accA.x += v2.x; accA.y += v2.y; accA.z += v2.z; accA.w += v2.w;
            accB.x += v3.x; accB.y += v3.y; accB.z += v3.z; accB.w += v3.w;
        }
        for (; j < nchunk; j++) {
            int s = __shfl_sync(0xffffffffu, idx, j);
            float4 v = __ldg(feats4 + (size_t)s * 32 + lane);
            accA.x += v.x; accA.y += v.y; accA.z += v.z; accA.w += v.w;
        }
    }

    float4 acc;
    acc.x = accA.x + accB.x;
    acc.y = accA.y + accB.y;
    acc.z = accA.z + accB.z;
    acc.w = accA.w + accB.w;

    float inv = 0.5f / fmaxf((float)deg, 1.0f);   // fold (1-alpha)=0.5
    float4 x = __ldg(feats4 + (size_t)node * 32 + lane);
    float4 r;
    r.x = 0.5f * x.x + inv * acc.x;
    r.y = 0.5f * x.y + inv * acc.y;
    r.z = 0.5f * x.z + inv * acc.z;
    r.w = 0.5f * x.w + inv * acc.w;
    out4[(size_t)node * 32 + lane] = r;
}

// ---------------------------------------------------------------------------
// Launch: d_in[0]=edge_feats [N*128] f32, d_in[1]=src [E] i32, d_in[2]=dst [E] i32
// ---------------------------------------------------------------------------
extern "C" void kernel_launch(void* const* d_in, const int* in_sizes, int n_in,
                              void* d_out, int out_size) {
    const float* feats = (const float*)d_in[0];
    const int* src = (const int*)d_in[1];
    const int* dst = (const int*)d_in[2];
    float* out = (float*)d_out;

    const int D = 128;
    const int n_nodes = in_sizes[0] / D;
    const int n_edges = in_sizes[1];
    const int ne4 = n_edges / 4;

    int *cur, *srcs;
    cudaGetSymbolAddress((void**)&cur, g_cur);
    cudaGetSymbolAddress((void**)&srcs, g_srcs);

    // 1. bucket fill (4 edges/thread); cur == 0 on entry (reset by gather)
    fill_kernel<<<(ne4 + 255) / 256, 256>>>((const int4*)src, (const int4*)dst,
                                            cur, srcs, ne4, n_edges);
    // 2. fp32 pull-gather + finalize (+ cur reset)
    {
        long total = (long)n_nodes * 32;
        gather_kernel<<<(int)((total + 255) / 256), 256>>>(
            (const float4*)feats, cur, srcs, (float4*)out, n_nodes);
    }
}

// round 12
// speedup vs baseline: 1.7654x; 1.7654x over previous
#include <cuda_runtime.h>
#include <cuda_fp16.h>

// ---------------------------------------------------------------------------
// Static device scratch (no allocations allowed).
// N = 100000 nodes, E = 1600000 edges, D = 128.
// Padded buckets: capacity 128/node (Poisson mean 16, max over 100K ~45;
// guarded, gather divides by min(deg, CAP) so always self-consistent).
// g_cur is zero at module load; gather_kernel resets each node's entry AFTER
// its accumulation loop (post-loop, own-warp program order), so every
// invocation -- including graph replays -- sees cur == 0 at prep_fill entry.
// ---------------------------------------------------------------------------
#define MAX_NODES 100000
#define BUCKET_CAP 128

__device__ __align__(16) int    g_cur[MAX_NODES];                   // degree/cursor
__device__ __align__(16) int    g_srcs[(size_t)MAX_NODES * BUCKET_CAP];
__device__ __align__(16) __half g_half[(size_t)MAX_NODES * 128];    // fp16 feats

// ---------------------------------------------------------------------------
// 1. prep_fill (fused; R6-measured 25.8us): bucket fill (ATOMG-latency-bound)
//    overlapped with the fp32->fp16 feature convert (DRAM-bound). Disjoint
//    data, no intra-kernel ordering needed. cur[] is zero on entry.
// ---------------------------------------------------------------------------
__global__ void prep_fill_kernel(const float4* __restrict__ feats4,
                                 uint2* __restrict__ half4,
                                 const int4* __restrict__ src4,
                                 const int4* __restrict__ dst4,
                                 int* __restrict__ cur,
                                 int* __restrict__ srcs,
                                 long nf4, int ne4, int n_edges) {
    long i = (long)blockIdx.x * blockDim.x + threadIdx.x;
    long stride = (long)gridDim.x * blockDim.x;

    // fill: 4 edges per iteration, 4 independent ATOMGs in flight
    for (long j = i; j < ne4; j += stride) {
        int4 d = __ldg(dst4 + j);
        int4 s = __ldg(src4 + j);
        int p0 = atomicAdd(cur + d.x, 1);
        int p1 = atomicAdd(cur + d.y, 1);
        int p2 = atomicAdd(cur + d.z, 1);
        int p3 = atomicAdd(cur + d.w, 1);
        if (p0 < BUCKET_CAP) srcs[(size_t)d.x * BUCKET_CAP + p0] = s.x;
        if (p1 < BUCKET_CAP) srcs[(size_t)d.y * BUCKET_CAP + p1] = s.y;
        if (p2 < BUCKET_CAP) srcs[(size_t)d.z * BUCKET_CAP + p2] = s.z;
        if (p3 < BUCKET_CAP) srcs[(size_t)d.w * BUCKET_CAP + p3] = s.w;
    }
    if (i == 0) {  // tail (n_edges % 4)
        const int* src = (const int*)src4;
        const int* dst = (const int*)dst4;
        for (int e = ne4 * 4; e < n_edges; e++) {
            int d = dst[e];
            int p = atomicAdd(cur + d, 1);
            if (p < BUCKET_CAP) srcs[(size_t)d * BUCKET_CAP + p] = src[e];
        }
    }

    // convert: fp32 float4 -> 4x fp16 (uint2), same node*32+lane layout
    for (long j = i; j < nf4; j += stride) {
        float4 v = __ldg(feats4 + j);
        __half2 a = __floats2half2_rn(v.x, v.y);
        __half2 b = __floats2half2_rn(v.z, v.w);
        uint2 o;
        o.x = *reinterpret_cast<unsigned*>(&a);
        o.y = *reinterpret_cast<unsigned*>(&b);
        half4[j] = o;
    }
}

// ---------------------------------------------------------------------------
// 2. gather + finalize: VERBATIM R5 hot loop (measured-good class: fp16 uint2
//    __ldg loads, fp32 A/B loop-carried accumulators, unroll 4, degree via
//    __ldg). Cross-round evidence: every gather with a pre-loop plain-load +
//    store of cur ran 175-210us; every __ldg-read-only-before-loop gather ran
//    ~55us. Hence the cur reset is a single lane-0 store placed AFTER the
//    accumulation loop. out = 0.5*x + 0.5*sum/max(deg,1).
// ---------------------------------------------------------------------------
__device__ __forceinline__ void acc_add(float4& acc, uint2 u) {
    __half2 h0 = *reinterpret_cast<__half2*>(&u.x);
    __half2 h1 = *reinterpret_cast<__half2*>(&u.y);
    float2 f0 = __half22float2(h0);
    float2 f1 = __half22float2(h1);
    acc.x += f0.x; acc.y += f0.y; acc.z += f1.x; acc.w += f1.y;
}

__global__ void gather_kernel(const float4* __restrict__ feats4,
                              const uint2* __restrict__ half4,
                              int* __restrict__ cur,
                              const int* __restrict__ srcs,
                              float4* __restrict__ out4, int n_nodes) {
    int tid = blockIdx.x * blockDim.x + threadIdx.x;
    int node = tid >> 5;
    int lane = tid & 31;
    if (node >= n_nodes) return;

    int deg = min(__ldg(cur + node), BUCKET_CAP);
    const int* bucket = srcs + (size_t)node * BUCKET_CAP;

    float4 accA = make_float4(0.f, 0.f, 0.f, 0.f);
    float4 accB = make_float4(0.f, 0.f, 0.f, 0.f);

    for (int base = 0; base < deg; base += 32) {
        int nchunk = min(32, deg - base);
        int idx = (lane < nchunk) ? __ldg(bucket + base + lane) : 0;
        int j = 0;
        for (; j + 4 <= nchunk; j += 4) {
            int s0 = __shfl_sync(0xffffffffu, idx, j);
            int s1 = __shfl_sync(0xffffffffu, idx, j + 1);
            int s2 = __shfl_sync(0xffffffffu, idx, j + 2);
            int s3 = __shfl_sync(0xffffffffu, idx, j + 3);
            uint2 u0 = __ldg(half4 + (size_t)s0 * 32 + lane);
            uint2 u1 = __ldg(half4 + (size_t)s1 * 32 + lane);
            uint2 u2 = __ldg(half4 + (size_t)s2 * 32 + lane);
            uint2 u3 = __ldg(half4 + (size_t)s3 * 32 + lane);
            acc_add(accA, u0);
            acc_add(accB, u1);
            acc_add(accA, u2);
            acc_add(accB, u3);
        }
        for (; j < nchunk; j++) {
            int s = __shfl_sync(0xffffffffu, idx, j);
            uint2 u = __ldg(half4 + (size_t)s * 32 + lane);
            acc_add(accA, u);
        }
    }

    float4 acc;
    acc.x = accA.x + accB.x;
    acc.y = accA.y + accB.y;
    acc.z = accA.z + accB.z;
    acc.w = accA.w + accB.w;

    float inv = 0.5f / fmaxf((float)deg, 1.0f);   // fold (1-alpha)=0.5
    float4 x = __ldg(feats4 + (size_t)node * 32 + lane);
    float4 r;
    r.x = 0.5f * x.x + inv * acc.x;
    r.y = 0.5f * x.y + inv * acc.y;
    r.z = 0.5f * x.z + inv * acc.z;
    r.w = 0.5f * x.w + inv * acc.w;
    out4[(size_t)node * 32 + lane] = r;

    // reset cursor for the next invocation -- AFTER the hot loop; this warp
    // is the only reader/writer of cur[node], program order makes it safe.
    if (lane == 0) cur[node] = 0;
}

// ---------------------------------------------------------------------------
// Launch: d_in[0]=edge_feats [N*128] f32, d_in[1]=src [E] i32, d_in[2]=dst [E] i32
// ---------------------------------------------------------------------------
extern "C" void kernel_launch(void* const* d_in, const int* in_sizes, int n_in,
                              void* d_out, int out_size) {
    const float* feats = (const float*)d_in[0];
    const int* src = (const int*)d_in[1];
    const int* dst = (const int*)d_in[2];
    float* out = (float*)d_out;

    const int D = 128;
    const int n_nodes = in_sizes[0] / D;
    const int n_edges = in_sizes[1];
    const long nf4 = (long)n_nodes * (D / 4);
    const int ne4 = n_edges / 4;

    int *cur, *srcs;
    __half* halfp;
    cudaGetSymbolAddress((void**)&cur, g_cur);
    cudaGetSymbolAddress((void**)&srcs, g_srcs);
    cudaGetSymbolAddress((void**)&halfp, g_half);

    // 1. fused fill + convert (cur == 0 on entry; reset by previous gather)
    prep_fill_kernel<<<2048, 256>>>((const float4*)feats, (uint2*)halfp,
                                    (const int4*)src, (const int4*)dst,
                                    cur, srcs, nf4, ne4, n_edges);
    // 2. fp16 pull-gather + fp32 finalize (+ post-loop cur reset)
    {
        long total = (long)n_nodes * 32;
        gather_kernel<<<(int)((total + 255) / 256), 256>>>(
            (const float4*)feats, (const uint2*)halfp, cur, srcs,
            (float4*)out, n_nodes);
    }
}

// round 15
// speedup vs baseline: 2.2454x; 1.2719x over previous
#include <cuda_runtime.h>
#include <cuda_fp16.h>

// ---------------------------------------------------------------------------
// Static device scratch (no allocations allowed).
// N = 100000 nodes, E = 1600000 edges, D = 128.
// Padded buckets: capacity 128/node (Poisson mean 16, max over 100K ~45;
// guarded, gather divides by min(deg, CAP) so always self-consistent).
// Cursor lifecycle: zero_cur_kernel zeroes g_cur at the START of every
// launch (measured rounds R6/R7/R9/R12 showed ANY cur store inside
// gather_kernel degrades it 1.6-3.8x -- gather is strictly read-only on cur).
// ---------------------------------------------------------------------------
#define MAX_NODES 100000
#define BUCKET_CAP 128

__device__ __align__(16) int    g_cur[MAX_NODES];                   // degree/cursor
__device__ __align__(16) int    g_srcs[(size_t)MAX_NODES * BUCKET_CAP];
__device__ __align__(16) __half g_half[(size_t)MAX_NODES * 128];    // fp16 feats

// ---------------------------------------------------------------------------
// 0. zero cursors: 400 KB int4 memset. ~1us exec + launch overhead.
// ---------------------------------------------------------------------------
__global__ void zero_cur_kernel(int4* __restrict__ cur4, int n4) {
    int i = blockIdx.x * blockDim.x + threadIdx.x;
    if (i < n4) cur4[i] = make_int4(0, 0, 0, 0);
}

// ---------------------------------------------------------------------------
// 1. prep_fill (fused; measured 25.8us in R12): bucket fill (ATOMG-latency-
//    bound) overlapped with the fp32->fp16 feature convert (DRAM-bound).
//    Disjoint data, no intra-kernel ordering needed. cur[] is zero on entry.
// ---------------------------------------------------------------------------
__global__ void prep_fill_kernel(const float4* __restrict__ feats4,
                                 uint2* __restrict__ half4,
                                 const int4* __restrict__ src4,
                                 const int4* __restrict__ dst4,
                                 int* __restrict__ cur,
                                 int* __restrict__ srcs,
                                 long nf4, int ne4, int n_edges) {
    long i = (long)blockIdx.x * blockDim.x + threadIdx.x;
    long stride = (long)gridDim.x * blockDim.x;

    // fill: 4 edges per iteration, 4 independent ATOMGs in flight
    for (long j = i; j < ne4; j += stride) {
        int4 d = __ldg(dst4 + j);
        int4 s = __ldg(src4 + j);
        int p0 = atomicAdd(cur + d.x, 1);
        int p1 = atomicAdd(cur + d.y, 1);
        int p2 = atomicAdd(cur + d.z, 1);
        int p3 = atomicAdd(cur + d.w, 1);
        if (p0 < BUCKET_CAP) srcs[(size_t)d.x * BUCKET_CAP + p0] = s.x;
        if (p1 < BUCKET_CAP) srcs[(size_t)d.y * BUCKET_CAP + p1] = s.y;
        if (p2 < BUCKET_CAP) srcs[(size_t)d.z * BUCKET_CAP + p2] = s.z;
        if (p3 < BUCKET_CAP) srcs[(size_t)d.w * BUCKET_CAP + p3] = s.w;
    }
    if (i == 0) {  // tail (n_edges % 4)
        const int* src = (const int*)src4;
        const int* dst = (const int*)dst4;
        for (int e = ne4 * 4; e < n_edges; e++) {
            int d = dst[e];
            int p = atomicAdd(cur + d, 1);
            if (p < BUCKET_CAP) srcs[(size_t)d * BUCKET_CAP + p] = src[e];
        }
    }

    // convert: fp32 float4 -> 4x fp16 (uint2), same node*32+lane layout
    for (long j = i; j < nf4; j += stride) {
        float4 v = __ldg(feats4 + j);
        __half2 a = __floats2half2_rn(v.x, v.y);
        __half2 b = __floats2half2_rn(v.z, v.w);
        uint2 o;
        o.x = *reinterpret_cast<unsigned*>(&a);
        o.y = *reinterpret_cast<unsigned*>(&b);
        half4[j] = o;
    }
}

// ---------------------------------------------------------------------------
// 2. gather + finalize: the measured-good configuration (R4: 54.3us,
//    issue=52%, occ=81%): fp16 uint2 __ldg loads, fp32 A/B loop-carried
//    accumulators, unroll 4, degree via __ldg from a CONST pointer, and
//    NO stores except the final output row. out = 0.5*x + 0.5*sum/max(deg,1).
// ---------------------------------------------------------------------------
__device__ __forceinline__ void acc_add(float4& acc, uint2 u) {
    __half2 h0 = *reinterpret_cast<__half2*>(&u.x);
    __half2 h1 = *reinterpret_cast<__half2*>(&u.y);
    float2 f0 = __half22float2(h0);
    float2 f1 = __half22float2(h1);
    acc.x += f0.x; acc.y += f0.y; acc.z += f1.x; acc.w += f1.y;
}

__global__ void gather_kernel(const float4* __restrict__ feats4,
                              const uint2* __restrict__ half4,
                              const int* __restrict__ cur,
                              const int* __restrict__ srcs,
                              float4* __restrict__ out4, int n_nodes) {
    int tid = blockIdx.x * blockDim.x + threadIdx.x;
    int node = tid >> 5;
    int lane = tid & 31;
    if (node >= n_nodes) return;

    int deg = min(__ldg(cur + node), BUCKET_CAP);
    const int* bucket = srcs + (size_t)node * BUCKET_CAP;

    float4 accA = make_float4(0.f, 0.f, 0.f, 0.f);
    float4 accB = make_float4(0.f, 0.f, 0.f, 0.f);

    for (int base = 0; base < deg; base += 32) {
        int nchunk = min(32, deg - base);
        int idx = (lane < nchunk) ? __ldg(bucket + base + lane) : 0;
        int j = 0;
        for (; j + 4 <= nchunk; j += 4) {
            int s0 = __shfl_sync(0xffffffffu, idx, j);
            int s1 = __shfl_sync(0xffffffffu, idx, j + 1);
            int s2 = __shfl_sync(0xffffffffu, idx, j + 2);
            int s3 = __shfl_sync(0xffffffffu, idx, j + 3);
            uint2 u0 = __ldg(half4 + (size_t)s0 * 32 + lane);
            uint2 u1 = __ldg(half4 + (size_t)s1 * 32 + lane);
            uint2 u2 = __ldg(half4 + (size_t)s2 * 32 + lane);
            uint2 u3 = __ldg(half4 + (size_t)s3 * 32 + lane);
            acc_add(accA, u0);
            acc_add(accB, u1);
            acc_add(accA, u2);
            acc_add(accB, u3);
        }
        for (; j < nchunk; j++) {
            int s = __shfl_sync(0xffffffffu, idx, j);
            uint2 u = __ldg(half4 + (size_t)s * 32 + lane);
            acc_add(accA, u);
        }
    }

    float4 acc;
    acc.x = accA.x + accB.x;
    acc.y = accA.y + accB.y;
    acc.z = accA.z + accB.z;
    acc.w = accA.w + accB.w;

    float inv = 0.5f / fmaxf((float)deg, 1.0f);   // fold (1-alpha)=0.5
    float4 x = __ldg(feats4 + (size_t)node * 32 + lane);
    float4 r;
    r.x = 0.5f * x.x + inv * acc.x;
    r.y = 0.5f * x.y + inv * acc.y;
    r.z = 0.5f * x.z + inv * acc.z;
    r.w = 0.5f * x.w + inv * acc.w;
    out4[(size_t)node * 32 + lane] = r;
}

// ---------------------------------------------------------------------------
// Launch: d_in[0]=edge_feats [N*128] f32, d_in[1]=src [E] i32, d_in[2]=dst [E] i32
// ---------------------------------------------------------------------------
extern "C" void kernel_launch(void* const* d_in, const int* in_sizes, int n_in,
                              void* d_out, int out_size) {
    const float* feats = (const float*)d_in[0];
    const int* src = (const int*)d_in[1];
    const int* dst = (const int*)d_in[2];
    float* out = (float*)d_out;

    const int D = 128;
    const int n_nodes = in_sizes[0] / D;
    const int n_edges = in_sizes[1];
    const long nf4 = (long)n_nodes * (D / 4);
    const int ne4 = n_edges / 4;

    int *cur, *srcs;
    __half* halfp;
    cudaGetSymbolAddress((void**)&cur, g_cur);
    cudaGetSymbolAddress((void**)&srcs, g_srcs);
    cudaGetSymbolAddress((void**)&halfp, g_half);

    // 0. zero cursors (400 KB; ~1us exec)
    {
        int n4 = (n_nodes + 3) / 4;
        zero_cur_kernel<<<(n4 + 255) / 256, 256>>>((int4*)cur, n4);
    }
    // 1. fused fill + convert
    prep_fill_kernel<<<2048, 256>>>((const float4*)feats, (uint2*)halfp,
                                    (const int4*)src, (const int4*)dst,
                                    cur, srcs, nf4, ne4, n_edges);
    // 2. fp16 pull-gather + fp32 finalize (strictly read-only except output)
    {
        long total = (long)n_nodes * 32;
        gather_kernel<<<(int)((total + 255) / 256), 256>>>(
            (const float4*)feats, (const uint2*)halfp, cur, srcs,
            (float4*)out, n_nodes);
    }
}